// round 2
// baseline (speedup 1.0000x reference)
#include <cuda_runtime.h>
#include <cooperative_groups.h>
#include <math.h>

namespace cg = cooperative_groups;

#define LSQ   8192
#define EDIM  300
#define HDIM  256
#define G3    768
#define GRU_CLUSTER 8

// ---------------- scratch (static device allocations; no cudaMalloc) -------
__device__ float g_gx  [LSQ * G3];        // sentence GRU input projections
__device__ float g_HS  [LSQ * HDIM];
__device__ float g_hsg [LSQ * HDIM];
__device__ float g_hsgT[HDIM * LSQ];
__device__ float g_A   [LSQ * HDIM];
__device__ float g_S   [67108864];        // 8192*8192 scores / unnormalized P
__device__ float g_rinv[LSQ];
__device__ float g_hapo[LSQ * HDIM];
__device__ float g_cat [LSQ * 2 * HDIM];
__device__ float g_htil[LSQ * HDIM];
__device__ float g_feat[LSQ * 3 * HDIM];
__device__ float g_hcs [LSQ * HDIM];
__device__ float g_e   [LSQ];
__device__ float g_red [2];
__device__ float g_hc  [HDIM];
__device__ float g_c0  [1];
__device__ float g_cvec[HDIM];
__device__ float g_hcS [HDIM];

// ---------------- helpers --------------------------------------------------
__device__ __forceinline__ float sigm(float x) { return 1.f / (1.f + __expf(-x)); }

__device__ __forceinline__ float warp_sum(float v) {
    #pragma unroll
    for (int o = 16; o; o >>= 1) v += __shfl_xor_sync(0xffffffffu, v, o);
    return v;
}
__device__ __forceinline__ float warp_max(float v) {
    #pragma unroll
    for (int o = 16; o; o >>= 1) v = fmaxf(v, __shfl_xor_sync(0xffffffffu, v, o));
    return v;
}

// ---------------- generic fp32 SGEMM: C = act(rscale[m]*(A @ B^T) + bias[n])
// A[M,K] row-major (lda), B[N,K] row-major (ldb). M,N multiples of 128.
template <int ACT>
__global__ void __launch_bounds__(256)
sgemm128(const float* __restrict__ A, int lda,
         const float* __restrict__ B, int ldb,
         float* __restrict__ C, int ldc,
         int M, int N, int K,
         const float* __restrict__ bias,
         const float* __restrict__ rscale)
{
    __shared__ float As[8][128];
    __shared__ float Bs[8][128];
    const int bm = blockIdx.y * 128, bn = blockIdx.x * 128;
    const int tid = threadIdx.x;
    const int ty = tid / 16, tx = tid % 16;
    const int lr = tid >> 1;          // 0..127
    const int lc = (tid & 1) * 4;     // 0 or 4

    float acc[8][8];
    #pragma unroll
    for (int i = 0; i < 8; i++)
        #pragma unroll
        for (int j = 0; j < 8; j++) acc[i][j] = 0.f;

    for (int k0 = 0; k0 < K; k0 += 8) {
        const float* Ap = A + (size_t)(bm + lr) * lda + k0 + lc;
        const float* Bp = B + (size_t)(bn + lr) * ldb + k0 + lc;
        #pragma unroll
        for (int i = 0; i < 4; i++) {
            As[lc + i][lr] = (k0 + lc + i < K) ? Ap[i] : 0.f;
            Bs[lc + i][lr] = (k0 + lc + i < K) ? Bp[i] : 0.f;
        }
        __syncthreads();
        #pragma unroll
        for (int kk = 0; kk < 8; kk++) {
            float a[8], b[8];
            *(float4*)&a[0] = *(const float4*)&As[kk][ty * 8];
            *(float4*)&a[4] = *(const float4*)&As[kk][ty * 8 + 4];
            *(float4*)&b[0] = *(const float4*)&Bs[kk][tx * 8];
            *(float4*)&b[4] = *(const float4*)&Bs[kk][tx * 8 + 4];
            #pragma unroll
            for (int i = 0; i < 8; i++)
                #pragma unroll
                for (int j = 0; j < 8; j++)
                    acc[i][j] += a[i] * b[j];
        }
        __syncthreads();
    }

    #pragma unroll
    for (int i = 0; i < 8; i++) {
        int m = bm + ty * 8 + i;
        float rs = rscale ? rscale[m] : 1.f;
        #pragma unroll
        for (int j = 0; j < 8; j++) {
            int n = bn + tx * 8 + j;
            float v = acc[i][j] * rs;
            if (bias) v += bias[n];
            if (ACT == 1) v = tanhf(v);
            C[(size_t)m * ldc + n] = v;
        }
    }
}

// ---------------- claim GRU (L=1) + c0 + cvec ------------------------------
__global__ void claim_kernel(const float* __restrict__ claim,
                             const float* __restrict__ wih,
                             const float* __restrict__ bih,
                             const float* __restrict__ bhh,
                             const float* __restrict__ gate_c_w,
                             const float* __restrict__ joint_w)
{
    __shared__ float sc[EDIM];
    __shared__ float gx[G3];
    __shared__ float hcs[HDIM];
    int tid = threadIdx.x;  // 768 threads
    for (int k = tid; k < EDIM; k += G3) sc[k] = claim[k];
    __syncthreads();

    float a = 0.f;
    const float* w = wih + (size_t)tid * EDIM;
    for (int k = 0; k < EDIM; k++) a += sc[k] * w[k];
    gx[tid] = a + bih[tid];
    __syncthreads();

    if (tid < HDIM) {
        float r = sigm(gx[tid] + bhh[tid]);
        float z = sigm(gx[HDIM + tid] + bhh[HDIM + tid]);
        float n = tanhf(gx[2 * HDIM + tid] + r * bhh[2 * HDIM + tid]);
        float h = (1.f - z) * n;     // h0 = 0
        hcs[tid] = h;
        g_hc[tid] = h;
    }
    __syncthreads();

    if (tid < 32) {
        float s = 0.f;
        for (int k = tid; k < HDIM; k += 32) s += hcs[k] * gate_c_w[k];
        s = warp_sum(s);
        if (tid == 0) g_c0[0] = s;
    }
    if (tid < HDIM) {
        float s = 0.f;
        const float* jw = joint_w + (size_t)tid * 1024;
        for (int k = 0; k < HDIM; k++) s += hcs[k] * jw[k];
        g_cvec[tid] = s;
    }
}

// ---------------- sentence GRU: persistent 8-CTA cluster -------------------
// whh lives in registers: 96 rows/CTA x 8 threads/row x 32 weights/thread.
__global__ void __cluster_dims__(GRU_CLUSTER, 1, 1) __launch_bounds__(768, 1)
gru_kernel(const float* __restrict__ whh,
           const float* __restrict__ bhh,
           const float* __restrict__ gx,
           float* __restrict__ HS, int T)
{
    cg::cluster_group cluster = cg::this_cluster();
    const unsigned rank = cluster.block_rank();

    __shared__ __align__(16) float hbuf[2][HDIM];
    __shared__ float gh[128];   // [0:32) r, [32:64) z, [64:96) hn, [96:128) gx_n

    const int tid = threadIdx.x;            // 768
    const int row_local = tid >> 3;         // 0..95
    const int kc = tid & 7;                 // k-chunk 0..7
    const int gate = row_local >> 5;        // 0,1,2
    const int j_local = row_local & 31;
    const int j_global = rank * 32 + j_local;
    const int wrow = gate * HDIM + j_global;

    // weights -> registers (32 per thread)
    float w[32];
    {
        const float4* wp = reinterpret_cast<const float4*>(whh + (size_t)wrow * HDIM + kc * 32);
        #pragma unroll
        for (int i = 0; i < 8; i++) {
            float4 v = wp[i];
            w[4 * i + 0] = v.x; w[4 * i + 1] = v.y;
            w[4 * i + 2] = v.z; w[4 * i + 3] = v.w;
        }
    }
    const float bias = bhh[wrow];

    if (tid < HDIM) { hbuf[0][tid] = 0.f; hbuf[1][tid] = 0.f; }
    cluster.sync();

    const float* gxp = gx + wrow;
    float gx_cur = (kc == 0) ? __ldg(gxp) : 0.f;

    for (int t = 0; t < T; t++) {
        // prefetch next step's gx while this step computes
        float gx_nxt = 0.f;
        if (kc == 0 && t + 1 < T) gx_nxt = __ldg(gxp + (size_t)(t + 1) * G3);

        const int p = t & 1;
        const float4* h4 = reinterpret_cast<const float4*>(&hbuf[p][kc * 32]);
        float a0 = 0.f, a1 = 0.f, a2 = 0.f, a3 = 0.f;
        #pragma unroll
        for (int i = 0; i < 8; i++) {
            float4 hv = h4[i];
            a0 += w[4 * i + 0] * hv.x;
            a1 += w[4 * i + 1] * hv.y;
            a2 += w[4 * i + 2] * hv.z;
            a3 += w[4 * i + 3] * hv.w;
        }
        float acc = (a0 + a1) + (a2 + a3);
        acc += __shfl_xor_sync(0xffffffffu, acc, 4);
        acc += __shfl_xor_sync(0xffffffffu, acc, 2);
        acc += __shfl_xor_sync(0xffffffffu, acc, 1);

        if (kc == 0) {
            if (gate == 2) { gh[64 + j_local] = acc + bias; gh[96 + j_local] = gx_cur; }
            else           { gh[gate * 32 + j_local] = acc + bias + gx_cur; }
        }
        __syncthreads();

        if (tid < 32) {
            const int j = tid;
            float r = sigm(gh[j]);
            float z = sigm(gh[32 + j]);
            float n = tanhf(gh[96 + j] + r * gh[64 + j]);
            float h_old = hbuf[p][rank * 32 + j];
            float h_new = (1.f - z) * n + z * h_old;
            HS[(size_t)t * HDIM + rank * 32 + j] = h_new;
            // broadcast slice to every CTA's other buffer (incl. self)
            #pragma unroll
            for (int c = 0; c < GRU_CLUSTER; c++) {
                float* dst = cluster.map_shared_rank(&hbuf[1 - p][rank * 32 + j], c);
                *dst = h_new;
            }
        }
        gx_cur = gx_nxt;
        cluster.sync();
    }
}

// ---------------- claim-gated sentence states ------------------------------
__global__ void gate_kernel(const float* __restrict__ HS,
                            const float* __restrict__ gate_s_w,
                            float* __restrict__ hsg)
{
    int row = blockIdx.x * blockDim.y + threadIdx.y;
    int lane = threadIdx.x;
    const float* h = HS + (size_t)row * HDIM;
    float s = 0.f;
    for (int k = lane; k < HDIM; k += 32) s += h[k] * gate_s_w[k];
    s = warp_sum(s);
    float g = sigm(s + g_c0[0]);
    for (int k = lane; k < HDIM; k += 32) {
        float hv = h[k];
        hsg[(size_t)row * HDIM + k] = g * hv + (1.f - g) * g_hc[k];
    }
}

// ---------------- row softmax over S (unnormalized exp kept, 1/sum stored) -
__global__ void softmax_rows(float* __restrict__ S, float* __restrict__ rinv)
{
    __shared__ float sm[8];
    __shared__ float s_bcast;
    const int row = blockIdx.x;
    float* p = S + (size_t)row * LSQ;
    const int tid = threadIdx.x;   // 256

    float m = -1e30f;
    for (int j = tid; j < LSQ; j += 256) m = fmaxf(m, p[j]);
    m = warp_max(m);
    if ((tid & 31) == 0) sm[tid >> 5] = m;
    __syncthreads();
    if (tid == 0) {
        float v = sm[0];
        for (int i = 1; i < 8; i++) v = fmaxf(v, sm[i]);
        s_bcast = v;
    }
    __syncthreads();
    const float bm = s_bcast;

    float s = 0.f;
    for (int j = tid; j < LSQ; j += 256) {
        float e = __expf(p[j] - bm);
        p[j] = e;
        s += e;
    }
    s = warp_sum(s);
    if ((tid & 31) == 0) sm[tid >> 5] = s;
    __syncthreads();
    if (tid == 0) {
        float v = 0.f;
        for (int i = 0; i < 8; i++) v += sm[i];
        rinv[row] = 1.f / v;
    }
}

// ---------------- transpose hs_g [8192,256] -> [256,8192] ------------------
__global__ void transpose_k(const float* __restrict__ in, float* __restrict__ out)
{
    __shared__ float t[32][33];
    int x = blockIdx.x * 32 + threadIdx.x;   // col in 'in' (0..255)
    int y0 = blockIdx.y * 32;
    for (int i = threadIdx.y; i < 32; i += 8)
        t[i][threadIdx.x] = in[(size_t)(y0 + i) * HDIM + x];
    __syncthreads();
    int ox = blockIdx.y * 32 + threadIdx.x;  // col in 'out' (= original row)
    int oy = blockIdx.x * 32;
    for (int i = threadIdx.y; i < 32; i += 8)
        out[(size_t)(oy + i) * LSQ + ox] = t[threadIdx.x][i];
}

// ---------------- concat [HS | h_apo] --------------------------------------
__global__ void concat_kernel(const float* __restrict__ HS,
                              const float* __restrict__ hapo,
                              float* __restrict__ cat)
{
    int idx = blockIdx.x * blockDim.x + threadIdx.x;   // LSQ*512 threads exactly
    int i = idx >> 9, d = idx & 511;
    cat[idx] = (d < HDIM) ? HS[(size_t)i * HDIM + d]
                          : hapo[(size_t)i * HDIM + d - HDIM];
}

// ---------------- feat3 = [h_til, hc*h_til, |hc - h_til|] ------------------
__global__ void feat_kernel(const float* __restrict__ htil, float* __restrict__ feat)
{
    int idx = blockIdx.x * blockDim.x + threadIdx.x;   // LSQ*768 threads exactly
    int i = idx / 768, d = idx % 768;
    int dd = d & 255;
    float ht = htil[(size_t)i * HDIM + dd];
    float hv = g_hc[dd];
    float v;
    if (d < 256) v = ht;
    else if (d < 512) v = hv * ht;
    else v = fabsf(hv - ht);
    feat[idx] = v;
}

// ---------------- entailment score per row ---------------------------------
__global__ void ent_kernel(const float* __restrict__ hcs,
                           const float* __restrict__ w,
                           const float* __restrict__ b,
                           float* __restrict__ e)
{
    int row = blockIdx.x * blockDim.y + threadIdx.y;
    int lane = threadIdx.x;
    const float* h = hcs + (size_t)row * HDIM;
    float s = 0.f;
    for (int k = lane; k < HDIM; k += 32) s += h[k] * w[k];
    s = warp_sum(s);
    if (lane == 0) e[row] = tanhf(s + b[0]);
}

// ---------------- softmax(e) reduction scalars + zero hcS ------------------
__global__ void reduce_e_kernel(const float* __restrict__ e)
{
    __shared__ float sm[32];
    __shared__ float s_max;
    int tid = threadIdx.x;  // 1024
    float m = -1e30f;
    for (int i = tid; i < LSQ; i += 1024) m = fmaxf(m, e[i]);
    m = warp_max(m);
    if ((tid & 31) == 0) sm[tid >> 5] = m;
    __syncthreads();
    if (tid == 0) {
        float v = sm[0];
        for (int i = 1; i < 32; i++) v = fmaxf(v, sm[i]);
        s_max = v;
        g_red[0] = v;
    }
    __syncthreads();
    float mx = s_max;
    float s = 0.f;
    for (int i = tid; i < LSQ; i += 1024) s += __expf(e[i] - mx);
    s = warp_sum(s);
    if ((tid & 31) == 0) sm[tid >> 5] = s;
    __syncthreads();
    if (tid == 0) {
        float v = 0.f;
        for (int i = 0; i < 32; i++) v += sm[i];
        g_red[1] = v;
    }
    if (tid < HDIM) g_hcS[tid] = 0.f;
}

// ---------------- h_c_S = sum_i a_i * h_c_s[i] -----------------------------
__global__ void weighted_sum_kernel(const float* __restrict__ e,
                                    const float* __restrict__ hcs)
{
    __shared__ float sa[256];
    int d = threadIdx.x;                 // 256
    int r0 = blockIdx.x * 256;           // 32 blocks
    float mx = g_red[0], inv = 1.f / g_red[1];
    sa[d] = __expf(e[r0 + d] - mx) * inv;
    __syncthreads();
    float acc = 0.f;
    for (int rr = 0; rr < 256; rr++)
        acc += sa[rr] * hcs[(size_t)(r0 + rr) * HDIM + d];
    atomicAdd(&g_hcS[d], acc);
}

// ---------------- final logits + softmax -----------------------------------
__global__ void final_kernel(const float* __restrict__ fw,
                             const float* __restrict__ fb,
                             float* __restrict__ out)
{
    __shared__ float lg[3];
    int warp = threadIdx.x >> 5, lane = threadIdx.x & 31;
    if (warp < 3) {
        float s = 0.f;
        for (int k = lane; k < HDIM; k += 32) s += g_hcS[k] * fw[warp * HDIM + k];
        s = warp_sum(s);
        if (lane == 0) lg[warp] = s + fb[warp];
    }
    __syncthreads();
    if (threadIdx.x == 0) {
        float m = fmaxf(lg[0], fmaxf(lg[1], lg[2]));
        float e0 = __expf(lg[0] - m), e1 = __expf(lg[1] - m), e2 = __expf(lg[2] - m);
        float inv = 1.f / (e0 + e1 + e2);
        out[0] = e0 * inv; out[1] = e1 * inv; out[2] = e2 * inv;
    }
}

// ---------------- launch ---------------------------------------------------
extern "C" void kernel_launch(void* const* d_in, const int* in_sizes, int n_in,
                              void* d_out, int out_size)
{
    const float* claim     = (const float*)d_in[0];
    const float* sentences = (const float*)d_in[1];
    const float* c_wih     = (const float*)d_in[2];
    // c_whh (d_in[3]) unused: h0 = 0 so gh = c_bhh for the single claim step
    const float* c_bih     = (const float*)d_in[4];
    const float* c_bhh     = (const float*)d_in[5];
    const float* s_wih     = (const float*)d_in[6];
    const float* s_whh     = (const float*)d_in[7];
    const float* s_bih     = (const float*)d_in[8];
    const float* s_bhh     = (const float*)d_in[9];
    const float* gate_s_w  = (const float*)d_in[10];
    const float* gate_c_w  = (const float*)d_in[11];
    const float* atten_c_w = (const float*)d_in[12];
    const float* atten_c_b = (const float*)d_in[13];
    // atten_s_w / atten_s_b (14,15): per-row constant in scores -> cancels in softmax
    const float* ext_w     = (const float*)d_in[16];
    const float* ext_b     = (const float*)d_in[17];
    const float* joint_w   = (const float*)d_in[18];
    const float* ent_w     = (const float*)d_in[19];
    const float* ent_b     = (const float*)d_in[20];
    const float* final_w   = (const float*)d_in[21];
    const float* final_b   = (const float*)d_in[22];
    float* out = (float*)d_out;

    float *p_gx, *p_HS, *p_hsg, *p_hsgT, *p_A, *p_S, *p_rinv, *p_hapo,
          *p_cat, *p_htil, *p_feat, *p_hcs, *p_e, *p_cvec;
    cudaGetSymbolAddress((void**)&p_gx,   g_gx);
    cudaGetSymbolAddress((void**)&p_HS,   g_HS);
    cudaGetSymbolAddress((void**)&p_hsg,  g_hsg);
    cudaGetSymbolAddress((void**)&p_hsgT, g_hsgT);
    cudaGetSymbolAddress((void**)&p_A,    g_A);
    cudaGetSymbolAddress((void**)&p_S,    g_S);
    cudaGetSymbolAddress((void**)&p_rinv, g_rinv);
    cudaGetSymbolAddress((void**)&p_hapo, g_hapo);
    cudaGetSymbolAddress((void**)&p_cat,  g_cat);
    cudaGetSymbolAddress((void**)&p_htil, g_htil);
    cudaGetSymbolAddress((void**)&p_feat, g_feat);
    cudaGetSymbolAddress((void**)&p_hcs,  g_hcs);
    cudaGetSymbolAddress((void**)&p_e,    g_e);
    cudaGetSymbolAddress((void**)&p_cvec, g_cvec);

    // claim GRU + c0 + cvec
    claim_kernel<<<1, 768>>>(claim, c_wih, c_bih, c_bhh, gate_c_w, joint_w);

    // gx = sentences @ s_wih^T + s_bih   [8192, 768]
    sgemm128<0><<<dim3(G3 / 128, LSQ / 128), 256>>>(
        sentences, EDIM, s_wih, EDIM, p_gx, G3, LSQ, G3, EDIM, s_bih, nullptr);

    // sentence GRU (persistent cluster of 8)
    gru_kernel<<<GRU_CLUSTER, 768>>>(s_whh, s_bhh, p_gx, p_HS, LSQ);

    // claim-gated states
    gate_kernel<<<LSQ / 8, dim3(32, 8)>>>(p_HS, gate_s_w, p_hsg);

    // A = hs_g @ atten_c_w^T + atten_c_b   [8192, 256]
    sgemm128<0><<<dim3(HDIM / 128, LSQ / 128), 256>>>(
        p_hsg, HDIM, atten_c_w, HDIM, p_A, HDIM, LSQ, HDIM, HDIM, atten_c_b, nullptr);

    // S = A @ hs_g^T   [8192, 8192]
    sgemm128<0><<<dim3(LSQ / 128, LSQ / 128), 256>>>(
        p_A, HDIM, p_hsg, HDIM, p_S, LSQ, LSQ, LSQ, HDIM, nullptr, nullptr);

    // row softmax (keeps unnormalized exp; stores 1/rowsum)
    softmax_rows<<<LSQ, 256>>>(p_S, p_rinv);

    // hs_g^T for the PV GEMM
    transpose_k<<<dim3(HDIM / 32, LSQ / 32), dim3(32, 8)>>>(p_hsg, p_hsgT);

    // h_apo = diag(rinv) * P @ hs_g   [8192, 256]
    sgemm128<0><<<dim3(HDIM / 128, LSQ / 128), 256>>>(
        p_S, LSQ, p_hsgT, LSQ, p_hapo, HDIM, LSQ, HDIM, LSQ, nullptr, p_rinv);

    // h_til = tanh([HS | h_apo] @ ext_w^T + ext_b)
    concat_kernel<<<(LSQ * 512) / 1024, 1024>>>(p_HS, p_hapo, p_cat);
    sgemm128<1><<<dim3(HDIM / 128, LSQ / 128), 256>>>(
        p_cat, 2 * HDIM, ext_w, 2 * HDIM, p_htil, HDIM, LSQ, HDIM, 2 * HDIM, ext_b, nullptr);

    // h_c_s = tanh(cvec + feat3 @ joint_w[:,256:]^T)
    feat_kernel<<<(LSQ * 768) / 1024, 1024>>>(p_htil, p_feat);
    sgemm128<1><<<dim3(HDIM / 128, LSQ / 128), 256>>>(
        p_feat, 3 * HDIM, joint_w + HDIM, 4 * HDIM, p_hcs, HDIM, LSQ, HDIM, 3 * HDIM,
        p_cvec, nullptr);

    // e_i = tanh(h_c_s_i . ent_w + ent_b); softmax over rows; weighted sum; final
    ent_kernel<<<LSQ / 8, dim3(32, 8)>>>(p_hcs, ent_w, ent_b, p_e);
    reduce_e_kernel<<<1, 1024>>>(p_e);
    weighted_sum_kernel<<<LSQ / 256, 256>>>(p_e, p_hcs);
    final_kernel<<<1, 128>>>(final_w, final_b, out);
}